// round 7
// baseline (speedup 1.0000x reference)
#include <cuda_runtime.h>
#include <cstdint>

#define BB 8192
#define LL 200
#define QQ 128
#define HH 128
#define GRID 148
#define NTHREADS 1024
#define NWARPS 32

#define ROW_FLOATS (LL * HH)          // 25600
#define ROW_BYTES  (ROW_FLOATS * 4)   // 102400
#define W_BYTES    (QQ * HH * 4)      // 65536

__device__ float g_qw[BB * HH];       // qw = query @ W (4 MB, L2-resident)

// ---------------------------------------------------------------------------
// PTX helpers
// ---------------------------------------------------------------------------
__device__ __forceinline__ uint32_t smem_u32(const void* p) {
    uint32_t a;
    asm("{ .reg .u64 t; cvta.to.shared.u64 t, %1; cvt.u32.u64 %0, t; }"
        : "=r"(a) : "l"(p));
    return a;
}
__device__ __forceinline__ void mbar_init(uint32_t mbar, uint32_t count) {
    asm volatile("mbarrier.init.shared.b64 [%0], %1;" :: "r"(mbar), "r"(count) : "memory");
}
__device__ __forceinline__ void mbar_expect_tx(uint32_t mbar, uint32_t bytes) {
    asm volatile("mbarrier.arrive.expect_tx.shared.b64 _, [%0], %1;"
                 :: "r"(mbar), "r"(bytes) : "memory");
}
__device__ __forceinline__ void bulk_g2s(uint32_t dst, const void* src,
                                         uint32_t bytes, uint32_t mbar) {
    asm volatile(
        "cp.async.bulk.shared::cta.global.mbarrier::complete_tx::bytes "
        "[%0], [%1], %2, [%3];"
        :: "r"(dst), "l"(src), "r"(bytes), "r"(mbar) : "memory");
}
__device__ __forceinline__ void mbar_wait(uint32_t mbar, uint32_t parity) {
    uint32_t done;
    asm volatile(
        "{\n .reg .pred p;\n"
        " mbarrier.try_wait.parity.acquire.cta.shared::cta.b64 p, [%1], %2, 0x989680;\n"
        " selp.b32 %0, 1, 0, p;\n}"
        : "=r"(done) : "r"(mbar), "r"(parity) : "memory");
    while (!done) {
        asm volatile(
            "{\n .reg .pred p;\n"
            " mbarrier.try_wait.parity.acquire.cta.shared::cta.b64 p, [%1], %2, 0x989680;\n"
            " selp.b32 %0, 1, 0, p;\n}"
            : "=r"(done) : "r"(mbar), "r"(parity) : "memory");
    }
}

// ---------------------------------------------------------------------------
// Single persistent fused kernel. grid=148 (1 CTA/SM), 1024 threads.
//
// Prologue (per CTA): bulk-copy W into buf1[0:16384), LDG-stage this CTA's
// query rows into buf1[16384:...), GEMM -> g_qw rows for this CTA, all
// overlapped with the TMA copy of row(bid) into buf0.
//
// Main loop: double-buffered TMA row streaming, no-max softmax fused into
// pass 1 with mask-skipping, pass 2 SMEM-only, 2 barriers/row.
//
// SMEM (floats):
//   buf0 [0,25600) | buf1 [25600,51200) | s_logits [51200,51456)
//   s_red [51456,51492) (32 sums + int flag) | s_part [51492.. +4096)
//   mbar (3 x u64) @ float 55588  -> total 222376 B
// ---------------------------------------------------------------------------
__global__ __launch_bounds__(NTHREADS, 1) void attn_fused_kernel(
    const float* __restrict__ query, const float* __restrict__ W,
    const float* __restrict__ hist,  const void* __restrict__ hlen,
    float* __restrict__ out)
{
    extern __shared__ float smem[];
    float*  bufs[2] = { smem, smem + ROW_FLOATS };
    float*  s_logits = smem + 2 * ROW_FLOATS;          // 51200 (exp(logit))
    float*  s_red    = s_logits + 256;                 // 51456 (32 warp sums)
    int*    s_flag   = (int*)(s_red + 32);             // 51488
    float*  s_part   = s_red + 36;                     // 51492: [32][128]
    uint64_t* mbar   = (uint64_t*)(smem + 55588);      // 8B aligned

    const int tid  = threadIdx.x;
    const int warp = tid >> 5;
    const int lane = tid & 31;
    const int bid  = blockIdx.x;
    const int k    = lane & 7;      // column octet (0..7)
    const int r    = lane >> 3;     // row-in-group (0..3)

    const int nrows = (bid < (BB - 148 * (BB / 148))) ? (BB / 148 + 1) : (BB / 148);
    // BB/148 = 55, remainder 52 -> bid<52: 56 rows else 55

    const uint32_t m0 = smem_u32(&mbar[0]);
    const uint32_t m1 = smem_u32(&mbar[1]);
    const uint32_t mW = smem_u32(&mbar[2]);
    const uint32_t buf_a[2] = { smem_u32(bufs[0]), smem_u32(bufs[1]) };

    if (tid == 0) { mbar_init(m0, 1); mbar_init(m1, 1); mbar_init(mW, 1); }
    __syncthreads();

    // ---- prologue: kick off row0 copy + W copy; stage query; GEMM -> g_qw ----
    if (tid == 0) {
        mbar_expect_tx(m0, ROW_BYTES);
        bulk_g2s(buf_a[0], hist + (size_t)bid * ROW_FLOATS, ROW_BYTES, m0);
        mbar_expect_tx(mW, W_BYTES);
        bulk_g2s(buf_a[1], W, W_BYTES, mW);          // sW = buf1[0:16384)
        // length dtype: int64 values in [0,200) -> all odd dwords zero
        const int* len32 = (const int*)hlen;
        int nz = 0;
#pragma unroll
        for (int i = 1; i < 256; i += 2) nz += (len32[i] != 0);
        *s_flag = (nz == 0) ? 1 : 0;
    }

    // stage this CTA's query rows: sQ = buf1 + 16384 floats, [64][128]
    float* sQ = bufs[1] + QQ * HH;
    {
        const float4* Qg = (const float4*)query;
        float4* sQ4 = (float4*)sQ;
        for (int rr = warp; rr < nrows; rr += NWARPS) {
            const int b = bid + 148 * rr;
            sQ4[rr * 32 + lane] = Qg[(size_t)b * 32 + lane];
        }
    }
    mbar_wait(mW, 0);          // W resident in SMEM
    __syncthreads();           // sQ staged by all warps

    // GEMM: thread t -> row gr = t>>4 (0..63), col octet gj = t&15
    {
        const int gr = tid >> 4;
        const int gj = tid & 15;
        if (gr < nrows) {
            const float*  sQr = sQ + gr * QQ;
            const float4* sW4 = (const float4*)bufs[1];
            float acc[8];
#pragma unroll
            for (int c = 0; c < 8; ++c) acc[c] = 0.f;
#pragma unroll 4
            for (int q = 0; q < QQ; ++q) {
                const float qs = sQr[q];
                float4 w0 = sW4[q * 32 + gj * 2];
                float4 w1 = sW4[q * 32 + gj * 2 + 1];
                acc[0] = fmaf(qs, w0.x, acc[0]);
                acc[1] = fmaf(qs, w0.y, acc[1]);
                acc[2] = fmaf(qs, w0.z, acc[2]);
                acc[3] = fmaf(qs, w0.w, acc[3]);
                acc[4] = fmaf(qs, w1.x, acc[4]);
                acc[5] = fmaf(qs, w1.y, acc[5]);
                acc[6] = fmaf(qs, w1.z, acc[6]);
                acc[7] = fmaf(qs, w1.w, acc[7]);
            }
            const int b = bid + 148 * gr;
            float4 o0 = {acc[0], acc[1], acc[2], acc[3]};
            float4 o1 = {acc[4], acc[5], acc[6], acc[7]};
            float* dst = g_qw + (size_t)b * HH + gj * 8;
            *(float4*)dst       = o0;
            *(float4*)(dst + 4) = o1;
        }
    }
    __syncthreads();           // buf1 free; g_qw (own rows) written
    const int is64 = *s_flag;

    // ---- main loop ----
    uint32_t ph0 = 0, ph1 = 0;
    int it = 0;
    for (int b = bid; b < BB; b += GRID, ++it) {
        const int cur = it & 1;

        // prefetch next row into the other buffer
        const int bn = b + GRID;
        if (bn < BB && tid == 0) {
            const uint32_t mb = cur ? m0 : m1;
            mbar_expect_tx(mb, ROW_BYTES);
            bulk_g2s(buf_a[cur ^ 1], hist + (size_t)bn * ROW_FLOATS, ROW_BYTES, mb);
        }

        // prefetch qw fragment + length while copy runs
        const float4* qw4 = (const float4*)(g_qw + (size_t)b * HH);
        float4 qv[4];
#pragma unroll
        for (int c = 0; c < 4; ++c) qv[c] = qw4[c * 8 + k];

        int Lb;
        if (is64) Lb = (int)((const long long*)hlen)[b];
        else      Lb = ((const int*)hlen)[b];

        // wait current buffer
        if (cur == 0) { mbar_wait(m0, ph0); ph0 ^= 1; }
        else          { mbar_wait(m1, ph1); ph1 ^= 1; }

        const float4* s4 = (const float4*)bufs[cur];

        // ---- pass 1: e_l = exp(logit_l); masked rows -> 1.0f; skip fully-
        // masked groups (warp-uniform predicate). 4 rows/group, 8 lanes/row.
        float wsum = 0.f;
        for (int g = warp; g < 50; g += NWARPS) {
            const int l = g * 4 + r;
            float e = 1.0f;                      // expf(1e-9f) == 1.0f
            if (g * 4 + 3 >= Lb) {
                const float4* row4 = s4 + l * 32;
                float p = 0.f;
#pragma unroll
                for (int c = 0; c < 4; ++c) {
                    float4 v = row4[c * 8 + k];
                    p += v.x * qv[c].x + v.y * qv[c].y + v.z * qv[c].z + v.w * qv[c].w;
                }
                p += __shfl_xor_sync(0xffffffffu, p, 4);
                p += __shfl_xor_sync(0xffffffffu, p, 2);
                p += __shfl_xor_sync(0xffffffffu, p, 1);
                if (l >= Lb) e = __expf(p);
            }
            if (k == 0) { s_logits[l] = e; wsum += e; }
        }
        // combine k==0 lanes (0,8,16,24)
        wsum += __shfl_xor_sync(0xffffffffu, wsum, 16);
        wsum += __shfl_xor_sync(0xffffffffu, wsum, 8);
        if (lane == 0) s_red[warp] = wsum;
        __syncthreads();

        // private 1/total (32 broadcast LDS, no extra barrier)
        float tot = 0.f;
#pragma unroll
        for (int w = 0; w < NWARPS; ++w) tot += s_red[w];
        const float inv = __frcp_rn(tot);

        // ---- pass 2: partial out per warp (SMEM only) ----
        float4 a4 = {0.f, 0.f, 0.f, 0.f};
        for (int l = warp; l < LL; l += NWARPS) {
            const float sc = s_logits[l];
            float4 v = s4[l * 32 + lane];
            a4.x = fmaf(sc, v.x, a4.x);
            a4.y = fmaf(sc, v.y, a4.y);
            a4.z = fmaf(sc, v.z, a4.z);
            a4.w = fmaf(sc, v.w, a4.w);
        }
        a4.x *= inv; a4.y *= inv; a4.z *= inv; a4.w *= inv;
        ((float4*)s_part)[warp * 32 + lane] = a4;
        __syncthreads();   // all buf[cur] reads done after this

        // ---- final reduce: 128 threads, conflict-free scalar columns ----
        if (tid < HH) {
            float vsum = 0.f;
#pragma unroll
            for (int g = 0; g < NWARPS; ++g) vsum += s_part[g * HH + tid];
            out[(size_t)b * HH + tid] = vsum;
        }
    }
}

// ---------------------------------------------------------------------------
extern "C" void kernel_launch(void* const* d_in, const int* in_sizes, int n_in,
                              void* d_out, int out_size) {
    // Bind inputs BY ELEMENT COUNT (all distinct) — immune to ordering.
    const float* query = nullptr;   // 1048576
    const float* hist  = nullptr;   // 209715200
    const void*  hlen  = nullptr;   // 8192
    const float* W     = nullptr;   // 16384
    for (int i = 0; i < n_in; ++i) {
        switch (in_sizes[i]) {
            case BB * QQ:      query = (const float*)d_in[i]; break;
            case BB * LL * HH: hist  = (const float*)d_in[i]; break;
            case BB:           hlen  = d_in[i];               break;
            case QQ * HH:      W     = (const float*)d_in[i]; break;
            default: break;
        }
    }
    float* out = (float*)d_out;

    const int smem = 55588 * 4 + 64;   // 222416 B

    cudaFuncSetAttribute(attn_fused_kernel,
                         cudaFuncAttributeMaxDynamicSharedMemorySize, smem);

    attn_fused_kernel<<<GRID, NTHREADS, smem>>>(query, W, hist, hlen, out);
}

// round 9
// speedup vs baseline: 1.5319x; 1.5319x over previous
#include <cuda_runtime.h>
#include <cstdint>

#define BB 8192
#define LL 200
#define QQ 128
#define HH 128
#define GRID 148
#define NTHREADS 768
#define NWARPS 24

#define ROW_FLOATS (LL * HH)          // 25600
#define ROW_BYTES  (ROW_FLOATS * 4)   // 102400
#define W_BYTES    (QQ * HH * 4)      // 65536

__device__ float g_qw[BB * HH];       // qw = query @ W (4 MB, L2-resident)

// ---------------------------------------------------------------------------
// PTX helpers
// ---------------------------------------------------------------------------
__device__ __forceinline__ uint32_t smem_u32(const void* p) {
    uint32_t a;
    asm("{ .reg .u64 t; cvta.to.shared.u64 t, %1; cvt.u32.u64 %0, t; }"
        : "=r"(a) : "l"(p));
    return a;
}
__device__ __forceinline__ void mbar_init(uint32_t mbar, uint32_t count) {
    asm volatile("mbarrier.init.shared.b64 [%0], %1;" :: "r"(mbar), "r"(count) : "memory");
}
__device__ __forceinline__ void mbar_expect_tx(uint32_t mbar, uint32_t bytes) {
    asm volatile("mbarrier.arrive.expect_tx.shared.b64 _, [%0], %1;"
                 :: "r"(mbar), "r"(bytes) : "memory");
}
__device__ __forceinline__ void bulk_g2s(uint32_t dst, const void* src,
                                         uint32_t bytes, uint32_t mbar) {
    asm volatile(
        "cp.async.bulk.shared::cta.global.mbarrier::complete_tx::bytes "
        "[%0], [%1], %2, [%3];"
        :: "r"(dst), "l"(src), "r"(bytes), "r"(mbar) : "memory");
}
__device__ __forceinline__ void mbar_wait(uint32_t mbar, uint32_t parity) {
    uint32_t done;
    asm volatile(
        "{\n .reg .pred p;\n"
        " mbarrier.try_wait.parity.acquire.cta.shared::cta.b64 p, [%1], %2, 0x989680;\n"
        " selp.b32 %0, 1, 0, p;\n}"
        : "=r"(done) : "r"(mbar), "r"(parity) : "memory");
    while (!done) {
        asm volatile(
            "{\n .reg .pred p;\n"
            " mbarrier.try_wait.parity.acquire.cta.shared::cta.b64 p, [%1], %2, 0x989680;\n"
            " selp.b32 %0, 1, 0, p;\n}"
            : "=r"(done) : "r"(mbar), "r"(parity) : "memory");
    }
}

// ---------------------------------------------------------------------------
// Single persistent fused kernel. grid=148 (1 CTA/SM), 768 threads (24 warps,
// 6/SMSP — RF cap 85 regs/thread, no spills).
//
// Prologue: bulk-copy W into buf1, LDG-stage this CTA's query rows, GEMM ->
// g_qw rows for this CTA, overlapped with the TMA copy of row(bid) into buf0.
// Main loop: double-buffered TMA row streaming, no-max softmax fused into
// pass 1 with mask-skipping, pass 2 SMEM-only, 2 barriers/row.
//
// SMEM (floats):
//   buf0 [0,25600) | buf1 [25600,51200) | s_logits [51200,51456)
//   s_red [51456,51488) | s_flag @51488 | s_part [51492,54564) (24x128)
//   mbar (3 x u64) @ float 54564  -> total ~218.3 KB
// ---------------------------------------------------------------------------
__global__ __launch_bounds__(NTHREADS, 1) void attn_fused_kernel(
    const float* __restrict__ query, const float* __restrict__ W,
    const float* __restrict__ hist,  const void* __restrict__ hlen,
    float* __restrict__ out)
{
    extern __shared__ float smem[];
    float*  bufs[2] = { smem, smem + ROW_FLOATS };
    float*  s_logits = smem + 2 * ROW_FLOATS;          // 51200 (exp(logit))
    float*  s_red    = s_logits + 256;                 // 51456 (24 warp sums)
    int*    s_flag   = (int*)(s_red + 32);             // 51488
    float*  s_part   = s_red + 36;                     // 51492: [24][128]
    uint64_t* mbar   = (uint64_t*)(smem + 54564);      // byte 218256, 8B aligned

    const int tid  = threadIdx.x;
    const int warp = tid >> 5;
    const int lane = tid & 31;
    const int bid  = blockIdx.x;
    const int k    = lane & 7;      // column octet (0..7)
    const int r    = lane >> 3;     // row-in-group (0..3)

    // BB = 55*148 + 52: bid<52 -> 56 rows, else 55
    const int nrows = (bid < (BB - 148 * (BB / 148))) ? (BB / 148 + 1) : (BB / 148);

    const uint32_t m0 = smem_u32(&mbar[0]);
    const uint32_t m1 = smem_u32(&mbar[1]);
    const uint32_t mW = smem_u32(&mbar[2]);
    const uint32_t buf_a[2] = { smem_u32(bufs[0]), smem_u32(bufs[1]) };

    if (tid == 0) { mbar_init(m0, 1); mbar_init(m1, 1); mbar_init(mW, 1); }
    __syncthreads();

    // ---- prologue: row0 copy + W copy; stage query; GEMM -> g_qw ----
    if (tid == 0) {
        mbar_expect_tx(m0, ROW_BYTES);
        bulk_g2s(buf_a[0], hist + (size_t)bid * ROW_FLOATS, ROW_BYTES, m0);
        mbar_expect_tx(mW, W_BYTES);
        bulk_g2s(buf_a[1], W, W_BYTES, mW);          // sW = buf1[0:16384)
        // length dtype: int64 values in [0,200) -> all odd dwords zero
        const int* len32 = (const int*)hlen;
        int nz = 0;
#pragma unroll
        for (int i = 1; i < 256; i += 2) nz += (len32[i] != 0);
        *s_flag = (nz == 0) ? 1 : 0;
    }

    // stage this CTA's query rows: sQ = buf1 + 16384 floats, [56][128] max
    float* sQ = bufs[1] + QQ * HH;
    {
        const float4* Qg = (const float4*)query;
        float4* sQ4 = (float4*)sQ;
        for (int rr = warp; rr < nrows; rr += NWARPS) {
            const int b = bid + 148 * rr;
            sQ4[rr * 32 + lane] = Qg[(size_t)b * 32 + lane];
        }
    }
    mbar_wait(mW, 0);          // W resident in SMEM
    __syncthreads();           // sQ staged by all warps

    // GEMM: 16 threads per row (col octet gj), rows strided by 48 groups
    {
        const int gj = tid & 15;
        const float4* sW4 = (const float4*)bufs[1];
        for (int gr = tid >> 4; gr < nrows; gr += NTHREADS / 16) {
            const float* sQr = sQ + gr * QQ;
            float acc[8];
#pragma unroll
            for (int c = 0; c < 8; ++c) acc[c] = 0.f;
#pragma unroll 4
            for (int q = 0; q < QQ; ++q) {
                const float qs = sQr[q];
                float4 w0 = sW4[q * 32 + gj * 2];
                float4 w1 = sW4[q * 32 + gj * 2 + 1];
                acc[0] = fmaf(qs, w0.x, acc[0]);
                acc[1] = fmaf(qs, w0.y, acc[1]);
                acc[2] = fmaf(qs, w0.z, acc[2]);
                acc[3] = fmaf(qs, w0.w, acc[3]);
                acc[4] = fmaf(qs, w1.x, acc[4]);
                acc[5] = fmaf(qs, w1.y, acc[5]);
                acc[6] = fmaf(qs, w1.z, acc[6]);
                acc[7] = fmaf(qs, w1.w, acc[7]);
            }
            const int b = bid + 148 * gr;
            float4 o0 = {acc[0], acc[1], acc[2], acc[3]};
            float4 o1 = {acc[4], acc[5], acc[6], acc[7]};
            float* dst = g_qw + (size_t)b * HH + gj * 8;
            *(float4*)dst       = o0;
            *(float4*)(dst + 4) = o1;
        }
    }
    __syncthreads();           // buf1 free; g_qw (own rows) written
    const int is64 = *s_flag;

    // ---- main loop ----
    uint32_t ph0 = 0, ph1 = 0;
    int it = 0;
    for (int b = bid; b < BB; b += GRID, ++it) {
        const int cur = it & 1;

        // prefetch next row into the other buffer
        const int bn = b + GRID;
        if (bn < BB && tid == 0) {
            const uint32_t mb = cur ? m0 : m1;
            mbar_expect_tx(mb, ROW_BYTES);
            bulk_g2s(buf_a[cur ^ 1], hist + (size_t)bn * ROW_FLOATS, ROW_BYTES, mb);
        }

        // prefetch qw fragment + length while copy runs
        const float4* qw4 = (const float4*)(g_qw + (size_t)b * HH);
        float4 qv[4];
#pragma unroll
        for (int c = 0; c < 4; ++c) qv[c] = qw4[c * 8 + k];

        int Lb;
        if (is64) Lb = (int)((const long long*)hlen)[b];
        else      Lb = ((const int*)hlen)[b];

        // wait current buffer
        if (cur == 0) { mbar_wait(m0, ph0); ph0 ^= 1; }
        else          { mbar_wait(m1, ph1); ph1 ^= 1; }

        const float4* s4 = (const float4*)bufs[cur];

        // ---- pass 1: e_l = exp(logit_l); masked rows -> 1.0f; skip fully-
        // masked groups (warp-uniform predicate). 4 rows/group, 8 lanes/row.
        float wsum = 0.f;
        for (int g = warp; g < 50; g += NWARPS) {
            const int l = g * 4 + r;
            float e = 1.0f;                      // expf(1e-9f) == 1.0f
            if (g * 4 + 3 >= Lb) {
                const float4* row4 = s4 + l * 32;
                float p = 0.f;
#pragma unroll
                for (int c = 0; c < 4; ++c) {
                    float4 v = row4[c * 8 + k];
                    p += v.x * qv[c].x + v.y * qv[c].y + v.z * qv[c].z + v.w * qv[c].w;
                }
                p += __shfl_xor_sync(0xffffffffu, p, 4);
                p += __shfl_xor_sync(0xffffffffu, p, 2);
                p += __shfl_xor_sync(0xffffffffu, p, 1);
                if (l >= Lb) e = __expf(p);
            }
            if (k == 0) { s_logits[l] = e; wsum += e; }
        }
        // combine k==0 lanes (0,8,16,24)
        wsum += __shfl_xor_sync(0xffffffffu, wsum, 16);
        wsum += __shfl_xor_sync(0xffffffffu, wsum, 8);
        if (lane == 0) s_red[warp] = wsum;
        __syncthreads();

        // private 1/total (24 broadcast LDS, no extra barrier)
        float tot = 0.f;
#pragma unroll
        for (int w = 0; w < NWARPS; ++w) tot += s_red[w];
        const float inv = __frcp_rn(tot);

        // ---- pass 2: partial out per warp (SMEM only) ----
        float4 a4 = {0.f, 0.f, 0.f, 0.f};
        for (int l = warp; l < LL; l += NWARPS) {
            const float sc = s_logits[l];
            float4 v = s4[l * 32 + lane];
            a4.x = fmaf(sc, v.x, a4.x);
            a4.y = fmaf(sc, v.y, a4.y);
            a4.z = fmaf(sc, v.z, a4.z);
            a4.w = fmaf(sc, v.w, a4.w);
        }
        a4.x *= inv; a4.y *= inv; a4.z *= inv; a4.w *= inv;
        ((float4*)s_part)[warp * 32 + lane] = a4;
        __syncthreads();   // all buf[cur] reads done after this

        // ---- final reduce: 128 threads, conflict-free scalar columns ----
        if (tid < HH) {
            float vsum = 0.f;
#pragma unroll
            for (int g = 0; g < NWARPS; ++g) vsum += s_part[g * HH + tid];
            out[(size_t)b * HH + tid] = vsum;
        }
    }
}

// ---------------------------------------------------------------------------
extern "C" void kernel_launch(void* const* d_in, const int* in_sizes, int n_in,
                              void* d_out, int out_size) {
    // Bind inputs BY ELEMENT COUNT (all distinct) — immune to ordering.
    const float* query = nullptr;   // 1048576
    const float* hist  = nullptr;   // 209715200
    const void*  hlen  = nullptr;   // 8192
    const float* W     = nullptr;   // 16384
    for (int i = 0; i < n_in; ++i) {
        switch (in_sizes[i]) {
            case BB * QQ:      query = (const float*)d_in[i]; break;
            case BB * LL * HH: hist  = (const float*)d_in[i]; break;
            case BB:           hlen  = d_in[i];               break;
            case QQ * HH:      W     = (const float*)d_in[i]; break;
            default: break;
        }
    }
    float* out = (float*)d_out;

    const int smem = 54564 * 4 + 64;   // 218320 B

    cudaFuncSetAttribute(attn_fused_kernel,
                         cudaFuncAttributeMaxDynamicSharedMemorySize, smem);

    attn_fused_kernel<<<GRID, NTHREADS, smem>>>(query, W, hist, hlen, out);
}

// round 11
// speedup vs baseline: 1.6951x; 1.1066x over previous
#include <cuda_runtime.h>
#include <cstdint>

#define BB 8192
#define LL 200
#define QQ 128
#define HH 128
#define GRID 148
#define NTHREADS 640
#define NWARPS 20

#define ROW_FLOATS (LL * HH)          // 25600
#define ROW_BYTES  (ROW_FLOATS * 4)   // 102400

__device__ float g_qw[BB * HH];       // qw = query @ W (4 MB, L2-resident)
__device__ int g_len_is64;

// ---------------------------------------------------------------------------
// PTX helpers
// ---------------------------------------------------------------------------
__device__ __forceinline__ uint32_t smem_u32(const void* p) {
    uint32_t a;
    asm("{ .reg .u64 t; cvta.to.shared.u64 t, %1; cvt.u32.u64 %0, t; }"
        : "=r"(a) : "l"(p));
    return a;
}
__device__ __forceinline__ void mbar_init(uint32_t mbar, uint32_t count) {
    asm volatile("mbarrier.init.shared.b64 [%0], %1;" :: "r"(mbar), "r"(count) : "memory");
}
__device__ __forceinline__ void mbar_expect_tx(uint32_t mbar, uint32_t bytes) {
    asm volatile("mbarrier.arrive.expect_tx.shared.b64 _, [%0], %1;"
                 :: "r"(mbar), "r"(bytes) : "memory");
}
__device__ __forceinline__ void bulk_g2s(uint32_t dst, const void* src,
                                         uint32_t bytes, uint32_t mbar) {
    asm volatile(
        "cp.async.bulk.shared::cta.global.mbarrier::complete_tx::bytes "
        "[%0], [%1], %2, [%3];"
        :: "r"(dst), "l"(src), "r"(bytes), "r"(mbar) : "memory");
}
__device__ __forceinline__ void mbar_wait(uint32_t mbar, uint32_t parity) {
    uint32_t done;
    asm volatile(
        "{\n .reg .pred p;\n"
        " mbarrier.try_wait.parity.acquire.cta.shared::cta.b64 p, [%1], %2, 0x989680;\n"
        " selp.b32 %0, 1, 0, p;\n}"
        : "=r"(done) : "r"(mbar), "r"(parity) : "memory");
    while (!done) {
        asm volatile(
            "{\n .reg .pred p;\n"
            " mbarrier.try_wait.parity.acquire.cta.shared::cta.b64 p, [%1], %2, 0x989680;\n"
            " selp.b32 %0, 1, 0, p;\n}"
            : "=r"(done) : "r"(mbar), "r"(parity) : "memory");
    }
}

// ---------------------------------------------------------------------------
// Kernel 1: qw = query @ W. 256 CTAs x 256 threads, 32 rows/CTA.
// Also detects length dtype (CTA 0).
// ---------------------------------------------------------------------------
__global__ __launch_bounds__(256, 2) void qw_gemm_kernel(
    const float* __restrict__ query, const float* __restrict__ W,
    const int* __restrict__ len32)
{
    extern __shared__ float smem1[];
    float* sW = smem1;                 // [128][128] = 16384
    float* sQ = smem1 + QQ * HH;       // [32][132] padded

    const int tid = threadIdx.x;
    const int b0  = blockIdx.x * 32;

    // len dtype detection: int64 values in [0,200) -> all odd dwords zero
    if (blockIdx.x == 0 && tid == 0) {
        int nz = 0;
#pragma unroll
        for (int i = 1; i < 256; i += 2) nz += (len32[i] != 0);
        g_len_is64 = (nz == 0) ? 1 : 0;
    }

    const float4* W4 = (const float4*)W;
    float4* sW4 = (float4*)sW;
#pragma unroll
    for (int i = 0; i < 16; ++i)
        sW4[tid + i * 256] = W4[tid + i * 256];

    const float4* Q4 = (const float4*)(query + (size_t)b0 * QQ);
#pragma unroll
    for (int i = 0; i < 4; ++i) {
        int idx = tid + i * 256;           // 0..1023
        int r = idx >> 5;
        int c = (idx & 31) << 2;
        float4 v = Q4[idx];
        *(float4*)&sQ[r * 132 + c] = v;
    }
    __syncthreads();

    const int j  = tid & 15;       // col octet
    const int i  = tid >> 4;       // row pair (0..15)
    const int r0 = i * 2;
    const int h0 = j * 8;

    float acc[2][8];
#pragma unroll
    for (int a = 0; a < 2; ++a)
#pragma unroll
        for (int c = 0; c < 8; ++c) acc[a][c] = 0.f;

#pragma unroll 4
    for (int q = 0; q < QQ; ++q) {
        float4 w0 = *(const float4*)&sW[q * HH + h0];
        float4 w1 = *(const float4*)&sW[q * HH + h0 + 4];
        float wv[8] = {w0.x, w0.y, w0.z, w0.w, w1.x, w1.y, w1.z, w1.w};
        float qv[2];
#pragma unroll
        for (int a = 0; a < 2; ++a) qv[a] = sQ[(r0 + a) * 132 + q];
#pragma unroll
        for (int a = 0; a < 2; ++a)
#pragma unroll
            for (int c = 0; c < 8; ++c)
                acc[a][c] = fmaf(qv[a], wv[c], acc[a][c]);
    }

#pragma unroll
    for (int a = 0; a < 2; ++a) {
        float4 o0 = {acc[a][0], acc[a][1], acc[a][2], acc[a][3]};
        float4 o1 = {acc[a][4], acc[a][5], acc[a][6], acc[a][7]};
        float* dst = g_qw + (size_t)(b0 + r0 + a) * HH + h0;
        *(float4*)dst       = o0;
        *(float4*)(dst + 4) = o1;
    }
}

// ---------------------------------------------------------------------------
// Kernel 2: persistent, double-buffered attention pooling.
// grid=148 (1 CTA/SM), 640 threads (20 warps, 5/SMSP, reg cap 102 -> no spill).
// Masked logit groups skipped entirely (rebalanced across warps); masked
// softmax contribution computed analytically (tot = Lb + sum of active exps).
// 2 barriers/row.
//
// SMEM (floats): buf0 [0,25600) | buf1 [25600,51200) | s_logits [51200,51456)
//   s_red [51456,51488) | s_part [51492,54052) (20x128) | mbar @ 54052
// ---------------------------------------------------------------------------
__global__ __launch_bounds__(NTHREADS, 1) void attn_pool_kernel(
    const float* __restrict__ hist, const void* __restrict__ hlen,
    float* __restrict__ out)
{
    extern __shared__ float smem[];
    float*  bufs[2] = { smem, smem + ROW_FLOATS };
    float*  s_logits = smem + 2 * ROW_FLOATS;          // 51200 (e_l for l>=Lb)
    float*  s_red    = s_logits + 256;                 // 51456 (20 warp sums)
    float*  s_part   = s_red + 36;                     // 51492: [20][128]
    uint64_t* mbar   = (uint64_t*)(smem + 54052);      // byte 216208, 8B aligned

    const int tid  = threadIdx.x;
    const int warp = tid >> 5;
    const int lane = tid & 31;
    const int bid  = blockIdx.x;
    const int k    = lane & 7;      // column octet (0..7)
    const int r    = lane >> 3;     // row-in-group (0..3)

    const uint32_t m0 = smem_u32(&mbar[0]);
    const uint32_t m1 = smem_u32(&mbar[1]);
    const uint32_t buf_a[2] = { smem_u32(bufs[0]), smem_u32(bufs[1]) };

    if (tid == 0) { mbar_init(m0, 1); mbar_init(m1, 1); }
    __syncthreads();

    const int is64 = g_len_is64;

    // prologue: first row into buf0
    if (tid == 0) {
        mbar_expect_tx(m0, ROW_BYTES);
        bulk_g2s(buf_a[0], hist + (size_t)bid * ROW_FLOATS, ROW_BYTES, m0);
    }

    uint32_t ph0 = 0, ph1 = 0;
    int it = 0;
    for (int b = bid; b < BB; b += GRID, ++it) {
        const int cur = it & 1;

        // prefetch next row into the other buffer (consumed last iteration)
        const int bn = b + GRID;
        if (bn < BB && tid == 0) {
            const uint32_t mb = cur ? m0 : m1;
            mbar_expect_tx(mb, ROW_BYTES);
            bulk_g2s(buf_a[cur ^ 1], hist + (size_t)bn * ROW_FLOATS, ROW_BYTES, mb);
        }

        // prefetch qw fragment + length while the copy runs
        const float4* qw4 = (const float4*)(g_qw + (size_t)b * HH);
        float4 qv[4];
#pragma unroll
        for (int c = 0; c < 4; ++c) qv[c] = qw4[c * 8 + k];

        int Lb;
        if (is64) Lb = (int)((const long long*)hlen)[b];
        else      Lb = ((const int*)hlen)[b];
        const int g0 = Lb >> 2;      // first group with any unmasked row

        // wait current buffer
        if (cur == 0) { mbar_wait(m0, ph0); ph0 ^= 1; }
        else          { mbar_wait(m1, ph1); ph1 ^= 1; }

        const float4* s4 = (const float4*)bufs[cur];

        // ---- pass 1: e_l = exp(logit_l) for l >= Lb only. Groups < g0 are
        // never visited; active groups rebalanced evenly across warps.
        // 4 rows/group, 8 lanes/row, 3 SHFL per group.
        float wsum = 0.f;
        for (int g = g0 + warp; g < 50; g += NWARPS) {
            const int l = g * 4 + r;
            const float4* row4 = s4 + l * 32;
            float p = 0.f;
#pragma unroll
            for (int c = 0; c < 4; ++c) {
                float4 v = row4[c * 8 + k];
                p += v.x * qv[c].x + v.y * qv[c].y + v.z * qv[c].z + v.w * qv[c].w;
            }
            p += __shfl_xor_sync(0xffffffffu, p, 4);
            p += __shfl_xor_sync(0xffffffffu, p, 2);
            p += __shfl_xor_sync(0xffffffffu, p, 1);
            float e = 0.f;
            if (l >= Lb) e = __expf(p);        // boundary-group masked lanes: 0
            if (k == 0) { s_logits[l] = e; wsum += e; }
        }
        // combine k==0 lanes (0,8,16,24)
        wsum += __shfl_xor_sync(0xffffffffu, wsum, 16);
        wsum += __shfl_xor_sync(0xffffffffu, wsum, 8);
        if (lane == 0) s_red[warp] = wsum;
        __syncthreads();

        // private 1/tot: masked rows contribute exactly 1.0 each (exp(1e-9))
        float t0 = 0.f, t1 = 0.f, t2 = 0.f, t3 = 0.f;
#pragma unroll
        for (int w = 0; w < NWARPS; w += 4) {
            t0 += s_red[w]; t1 += s_red[w + 1]; t2 += s_red[w + 2]; t3 += s_red[w + 3];
        }
        const float inv = __frcp_rn((float)Lb + ((t0 + t1) + (t2 + t3)));

        // ---- pass 2: out[h] = inv * sum_l w_l * hist[l][h] (SMEM only);
        // w_l = 1 for masked rows, e_l otherwise. 10 rows/warp exactly.
        float4 a4 = {0.f, 0.f, 0.f, 0.f};
        for (int l = warp; l < LL; l += NWARPS) {
            const float sc = (l < Lb) ? 1.0f : s_logits[l];
            float4 v = s4[l * 32 + lane];
            a4.x = fmaf(sc, v.x, a4.x);
            a4.y = fmaf(sc, v.y, a4.y);
            a4.z = fmaf(sc, v.z, a4.z);
            a4.w = fmaf(sc, v.w, a4.w);
        }
        a4.x *= inv; a4.y *= inv; a4.z *= inv; a4.w *= inv;
        ((float4*)s_part)[warp * 32 + lane] = a4;
        __syncthreads();   // all buf[cur] reads done after this

        // ---- final reduce: 128 threads, conflict-free scalar columns ----
        if (tid < HH) {
            float vsum = 0.f;
#pragma unroll
            for (int g = 0; g < NWARPS; ++g) vsum += s_part[g * HH + tid];
            out[(size_t)b * HH + tid] = vsum;
        }
    }
}

// ---------------------------------------------------------------------------
extern "C" void kernel_launch(void* const* d_in, const int* in_sizes, int n_in,
                              void* d_out, int out_size) {
    // Bind inputs BY ELEMENT COUNT (all distinct) — immune to ordering.
    const float* query = nullptr;   // 1048576
    const float* hist  = nullptr;   // 209715200
    const void*  hlen  = nullptr;   // 8192
    const float* W     = nullptr;   // 16384
    for (int i = 0; i < n_in; ++i) {
        switch (in_sizes[i]) {
            case BB * QQ:      query = (const float*)d_in[i]; break;
            case BB * LL * HH: hist  = (const float*)d_in[i]; break;
            case BB:           hlen  = d_in[i];               break;
            case QQ * HH:      W     = (const float*)d_in[i]; break;
            default: break;
        }
    }
    float* out = (float*)d_out;

    const int smem1 = (QQ * HH + 32 * 132) * (int)sizeof(float);   // 82432
    const int smem2 = 54052 * 4 + 64;                               // 216272

    cudaFuncSetAttribute(qw_gemm_kernel,
                         cudaFuncAttributeMaxDynamicSharedMemorySize, smem1);
    cudaFuncSetAttribute(attn_pool_kernel,
                         cudaFuncAttributeMaxDynamicSharedMemorySize, smem2);

    qw_gemm_kernel<<<BB / 32, 256, smem1>>>(query, W, (const int*)hlen);
    attn_pool_kernel<<<GRID, NTHREADS, smem2>>>(hist, hlen, out);
}

// round 12
// speedup vs baseline: 1.7485x; 1.0315x over previous
#include <cuda_runtime.h>
#include <cstdint>

#define BB 8192
#define LL 200
#define QQ 128
#define HH 128
#define GRID 148
#define NTHREADS 640
#define NWARPS 20

#define ROW_FLOATS (LL * HH)          // 25600
#define ROW_BYTES  (ROW_FLOATS * 4)   // 102400

__device__ float g_qw[BB * HH];       // qw = query @ W (4 MB, L2-resident)
__device__ int g_len_is64;

// ---------------------------------------------------------------------------
// PTX helpers
// ---------------------------------------------------------------------------
__device__ __forceinline__ uint32_t smem_u32(const void* p) {
    uint32_t a;
    asm("{ .reg .u64 t; cvta.to.shared.u64 t, %1; cvt.u32.u64 %0, t; }"
        : "=r"(a) : "l"(p));
    return a;
}
__device__ __forceinline__ void mbar_init(uint32_t mbar, uint32_t count) {
    asm volatile("mbarrier.init.shared.b64 [%0], %1;" :: "r"(mbar), "r"(count) : "memory");
}
__device__ __forceinline__ void mbar_expect_tx(uint32_t mbar, uint32_t bytes) {
    asm volatile("mbarrier.arrive.expect_tx.shared.b64 _, [%0], %1;"
                 :: "r"(mbar), "r"(bytes) : "memory");
}
__device__ __forceinline__ void bulk_g2s(uint32_t dst, const void* src,
                                         uint32_t bytes, uint32_t mbar) {
    asm volatile(
        "cp.async.bulk.shared::cta.global.mbarrier::complete_tx::bytes "
        "[%0], [%1], %2, [%3];"
        :: "r"(dst), "l"(src), "r"(bytes), "r"(mbar) : "memory");
}
__device__ __forceinline__ void mbar_wait(uint32_t mbar, uint32_t parity) {
    uint32_t done;
    asm volatile(
        "{\n .reg .pred p;\n"
        " mbarrier.try_wait.parity.acquire.cta.shared::cta.b64 p, [%1], %2, 0x989680;\n"
        " selp.b32 %0, 1, 0, p;\n}"
        : "=r"(done) : "r"(mbar), "r"(parity) : "memory");
    while (!done) {
        asm volatile(
            "{\n .reg .pred p;\n"
            " mbarrier.try_wait.parity.acquire.cta.shared::cta.b64 p, [%1], %2, 0x989680;\n"
            " selp.b32 %0, 1, 0, p;\n}"
            : "=r"(done) : "r"(mbar), "r"(parity) : "memory");
    }
}

// Packed f32x2 FMA (FFMA2) — only reachable via PTX; IEEE fp32 per half.
#define FMA_F32X2(d, a, b) \
    asm("fma.rn.f32x2 %0, %1, %2, %0;" : "+l"(d) : "l"(a), "l"(b))
#define PACK_SAME(d, fbits) \
    asm("mov.b64 %0, {%1, %1};" : "=l"(d) : "r"(fbits))
#define UNPACK2(lo, hi, p) \
    asm("mov.b64 {%0, %1}, %2;" : "=f"(lo), "=f"(hi) : "l"(p))

// ---------------------------------------------------------------------------
// Kernel 1: qw = query @ W. 128 CTAs x 256 threads, 64 rows/CTA.
// f32x2 packed FMA halves the FMA-pipe floor (~8us -> ~4us).
// Also detects length dtype (CTA 0).
// ---------------------------------------------------------------------------
__global__ __launch_bounds__(256, 2) void qw_gemm_kernel(
    const float* __restrict__ query, const float* __restrict__ W,
    const int* __restrict__ len32)
{
    extern __shared__ float smem1[];
    float* sW = smem1;                 // [128][128]
    float* sQ = smem1 + QQ * HH;       // [64][132] padded

    const int tid = threadIdx.x;
    const int b0  = blockIdx.x * 64;

    // len dtype detection: int64 values in [0,200) -> all odd dwords zero
    if (blockIdx.x == 0 && tid == 0) {
        int nz = 0;
#pragma unroll
        for (int i = 1; i < 256; i += 2) nz += (len32[i] != 0);
        g_len_is64 = (nz == 0) ? 1 : 0;
    }

    const float4* W4 = (const float4*)W;
    float4* sW4 = (float4*)sW;
#pragma unroll
    for (int i = 0; i < 16; ++i)
        sW4[tid + i * 256] = W4[tid + i * 256];

    const float4* Q4 = (const float4*)(query + (size_t)b0 * QQ);
#pragma unroll
    for (int i = 0; i < 8; ++i) {
        int idx = tid + i * 256;           // 0..2047
        int r = idx >> 5;
        int c = (idx & 31) << 2;
        float4 v = Q4[idx];
        *(float4*)&sQ[r * 132 + c] = v;
    }
    __syncthreads();

    const int j  = tid & 15;       // col octet
    const int i  = tid >> 4;       // row group (0..15)
    const int r0 = i * 4;
    const int h0 = j * 8;

    // 4 rows x 8 cols as 4x4 packed f32x2 accumulators
    uint64_t acc[4][4];
#pragma unroll
    for (int a = 0; a < 4; ++a)
#pragma unroll
        for (int c = 0; c < 4; ++c) acc[a][c] = 0ull;

#pragma unroll 4
    for (int q = 0; q < QQ; ++q) {
        // W row chunk: 8 floats = 4 packed pairs (64-bit lanes of LDS.128)
        const ulonglong2* wp = (const ulonglong2*)&sW[q * HH + h0];
        ulonglong2 wa = wp[0];   // {c0c1, c2c3}
        ulonglong2 wb = wp[1];   // {c4c5, c6c7}
#pragma unroll
        for (int a = 0; a < 4; ++a) {
            const uint32_t qb = __float_as_uint(sQ[(r0 + a) * 132 + q]);
            uint64_t qq; PACK_SAME(qq, qb);
            FMA_F32X2(acc[a][0], qq, wa.x);
            FMA_F32X2(acc[a][1], qq, wa.y);
            FMA_F32X2(acc[a][2], qq, wb.x);
            FMA_F32X2(acc[a][3], qq, wb.y);
        }
    }

#pragma unroll
    for (int a = 0; a < 4; ++a) {
        float o[8];
#pragma unroll
        for (int c = 0; c < 4; ++c) UNPACK2(o[2 * c], o[2 * c + 1], acc[a][c]);
        float* dst = g_qw + (size_t)(b0 + r0 + a) * HH + h0;
        float4 o0 = {o[0], o[1], o[2], o[3]};
        float4 o1 = {o[4], o[5], o[6], o[7]};
        *(float4*)dst       = o0;
        *(float4*)(dst + 4) = o1;
    }
}

// ---------------------------------------------------------------------------
// Kernel 2: persistent, double-buffered attention pooling (UNCHANGED from
// R11 — measured 138.3us, at the LTS/HBM effective ceiling ~6.2 TB/s).
// grid=148 (1 CTA/SM), 640 threads (20 warps).
// ---------------------------------------------------------------------------
__global__ __launch_bounds__(NTHREADS, 1) void attn_pool_kernel(
    const float* __restrict__ hist, const void* __restrict__ hlen,
    float* __restrict__ out)
{
    extern __shared__ float smem[];
    float*  bufs[2] = { smem, smem + ROW_FLOATS };
    float*  s_logits = smem + 2 * ROW_FLOATS;          // 51200 (e_l for l>=Lb)
    float*  s_red    = s_logits + 256;                 // 51456 (20 warp sums)
    float*  s_part   = s_red + 36;                     // 51492: [20][128]
    uint64_t* mbar   = (uint64_t*)(smem + 54052);      // byte 216208, 8B aligned

    const int tid  = threadIdx.x;
    const int warp = tid >> 5;
    const int lane = tid & 31;
    const int bid  = blockIdx.x;
    const int k    = lane & 7;      // column octet (0..7)
    const int r    = lane >> 3;     // row-in-group (0..3)

    const uint32_t m0 = smem_u32(&mbar[0]);
    const uint32_t m1 = smem_u32(&mbar[1]);
    const uint32_t buf_a[2] = { smem_u32(bufs[0]), smem_u32(bufs[1]) };

    if (tid == 0) { mbar_init(m0, 1); mbar_init(m1, 1); }
    __syncthreads();

    const int is64 = g_len_is64;

    // prologue: first row into buf0
    if (tid == 0) {
        mbar_expect_tx(m0, ROW_BYTES);
        bulk_g2s(buf_a[0], hist + (size_t)bid * ROW_FLOATS, ROW_BYTES, m0);
    }

    uint32_t ph0 = 0, ph1 = 0;
    int it = 0;
    for (int b = bid; b < BB; b += GRID, ++it) {
        const int cur = it & 1;

        // prefetch next row into the other buffer (consumed last iteration)
        const int bn = b + GRID;
        if (bn < BB && tid == 0) {
            const uint32_t mb = cur ? m0 : m1;
            mbar_expect_tx(mb, ROW_BYTES);
            bulk_g2s(buf_a[cur ^ 1], hist + (size_t)bn * ROW_FLOATS, ROW_BYTES, mb);
        }

        // prefetch qw fragment + length while the copy runs
        const float4* qw4 = (const float4*)(g_qw + (size_t)b * HH);
        float4 qv[4];
#pragma unroll
        for (int c = 0; c < 4; ++c) qv[c] = qw4[c * 8 + k];

        int Lb;
        if (is64) Lb = (int)((const long long*)hlen)[b];
        else      Lb = ((const int*)hlen)[b];
        const int g0 = Lb >> 2;      // first group with any unmasked row

        // wait current buffer
        if (cur == 0) { mbar_wait(m0, ph0); ph0 ^= 1; }
        else          { mbar_wait(m1, ph1); ph1 ^= 1; }

        const float4* s4 = (const float4*)bufs[cur];

        // ---- pass 1: e_l = exp(logit_l) for l >= Lb only; masked groups
        // skipped entirely, active groups rebalanced across warps.
        float wsum = 0.f;
        for (int g = g0 + warp; g < 50; g += NWARPS) {
            const int l = g * 4 + r;
            const float4* row4 = s4 + l * 32;
            float p = 0.f;
#pragma unroll
            for (int c = 0; c < 4; ++c) {
                float4 v = row4[c * 8 + k];
                p += v.x * qv[c].x + v.y * qv[c].y + v.z * qv[c].z + v.w * qv[c].w;
            }
            p += __shfl_xor_sync(0xffffffffu, p, 4);
            p += __shfl_xor_sync(0xffffffffu, p, 2);
            p += __shfl_xor_sync(0xffffffffu, p, 1);
            float e = 0.f;
            if (l >= Lb) e = __expf(p);        // boundary-group masked lanes: 0
            if (k == 0) { s_logits[l] = e; wsum += e; }
        }
        // combine k==0 lanes (0,8,16,24)
        wsum += __shfl_xor_sync(0xffffffffu, wsum, 16);
        wsum += __shfl_xor_sync(0xffffffffu, wsum, 8);
        if (lane == 0) s_red[warp] = wsum;
        __syncthreads();

        // private 1/tot: masked rows contribute exactly 1.0 each (exp(1e-9))
        float t0 = 0.f, t1 = 0.f, t2 = 0.f, t3 = 0.f;
#pragma unroll
        for (int w = 0; w < NWARPS; w += 4) {
            t0 += s_red[w]; t1 += s_red[w + 1]; t2 += s_red[w + 2]; t3 += s_red[w + 3];
        }
        const float inv = __frcp_rn((float)Lb + ((t0 + t1) + (t2 + t3)));

        // ---- pass 2: out[h] = inv * sum_l w_l * hist[l][h] (SMEM only);
        // w_l = 1 for masked rows, e_l otherwise. 10 rows/warp exactly.
        float4 a4 = {0.f, 0.f, 0.f, 0.f};
        for (int l = warp; l < LL; l += NWARPS) {
            const float sc = (l < Lb) ? 1.0f : s_logits[l];
            float4 v = s4[l * 32 + lane];
            a4.x = fmaf(sc, v.x, a4.x);
            a4.y = fmaf(sc, v.y, a4.y);
            a4.z = fmaf(sc, v.z, a4.z);
            a4.w = fmaf(sc, v.w, a4.w);
        }
        a4.x *= inv; a4.y *= inv; a4.z *= inv; a4.w *= inv;
        ((float4*)s_part)[warp * 32 + lane] = a4;
        __syncthreads();   // all buf[cur] reads done after this

        // ---- final reduce: 128 threads, conflict-free scalar columns ----
        if (tid < HH) {
            float vsum = 0.f;
#pragma unroll
            for (int g = 0; g < NWARPS; ++g) vsum += s_part[g * HH + tid];
            out[(size_t)b * HH + tid] = vsum;
        }
    }
}

// ---------------------------------------------------------------------------
extern "C" void kernel_launch(void* const* d_in, const int* in_sizes, int n_in,
                              void* d_out, int out_size) {
    // Bind inputs BY ELEMENT COUNT (all distinct) — immune to ordering.
    const float* query = nullptr;   // 1048576
    const float* hist  = nullptr;   // 209715200
    const void*  hlen  = nullptr;   // 8192
    const float* W     = nullptr;   // 16384
    for (int i = 0; i < n_in; ++i) {
        switch (in_sizes[i]) {
            case BB * QQ:      query = (const float*)d_in[i]; break;
            case BB * LL * HH: hist  = (const float*)d_in[i]; break;
            case BB:           hlen  = d_in[i];               break;
            case QQ * HH:      W     = (const float*)d_in[i]; break;
            default: break;
        }
    }
    float* out = (float*)d_out;

    const int smem1 = (QQ * HH + 64 * 132) * (int)sizeof(float);   // 99328
    const int smem2 = 54052 * 4 + 64;                               // 216272

    cudaFuncSetAttribute(qw_gemm_kernel,
                         cudaFuncAttributeMaxDynamicSharedMemorySize, smem1);
    cudaFuncSetAttribute(attn_pool_kernel,
                         cudaFuncAttributeMaxDynamicSharedMemorySize, smem2);

    qw_gemm_kernel<<<BB / 64, 256, smem1>>>(query, W, (const int*)hlen);
    attn_pool_kernel<<<GRID, NTHREADS, smem2>>>(hist, hlen, out);
}

// round 13
// speedup vs baseline: 1.7619x; 1.0077x over previous
#include <cuda_runtime.h>
#include <cstdint>

#define BB 8192
#define LL 200
#define QQ 128
#define HH 128
#define GRID 148
#define NTHREADS 640
#define NWARPS 20

#define ROW_FLOATS (LL * HH)          // 25600
#define ROW_BYTES  (ROW_FLOATS * 4)   // 102400

__device__ float g_qw[BB * HH];       // qw = query @ W (4 MB, L2-resident)
__device__ int g_len_is64;

// ---------------------------------------------------------------------------
// PTX helpers
// ---------------------------------------------------------------------------
__device__ __forceinline__ uint32_t smem_u32(const void* p) {
    uint32_t a;
    asm("{ .reg .u64 t; cvta.to.shared.u64 t, %1; cvt.u32.u64 %0, t; }"
        : "=r"(a) : "l"(p));
    return a;
}
__device__ __forceinline__ void mbar_init(uint32_t mbar, uint32_t count) {
    asm volatile("mbarrier.init.shared.b64 [%0], %1;" :: "r"(mbar), "r"(count) : "memory");
}
__device__ __forceinline__ void mbar_expect_tx(uint32_t mbar, uint32_t bytes) {
    asm volatile("mbarrier.arrive.expect_tx.shared.b64 _, [%0], %1;"
                 :: "r"(mbar), "r"(bytes) : "memory");
}
__device__ __forceinline__ void bulk_g2s(uint32_t dst, const void* src,
                                         uint32_t bytes, uint32_t mbar) {
    asm volatile(
        "cp.async.bulk.shared::cta.global.mbarrier::complete_tx::bytes "
        "[%0], [%1], %2, [%3];"
        :: "r"(dst), "l"(src), "r"(bytes), "r"(mbar) : "memory");
}
__device__ __forceinline__ void mbar_wait(uint32_t mbar, uint32_t parity) {
    uint32_t done;
    asm volatile(
        "{\n .reg .pred p;\n"
        " mbarrier.try_wait.parity.acquire.cta.shared::cta.b64 p, [%1], %2, 0x989680;\n"
        " selp.b32 %0, 1, 0, p;\n}"
        : "=r"(done) : "r"(mbar), "r"(parity) : "memory");
    while (!done) {
        asm volatile(
            "{\n .reg .pred p;\n"
            " mbarrier.try_wait.parity.acquire.cta.shared::cta.b64 p, [%1], %2, 0x989680;\n"
            " selp.b32 %0, 1, 0, p;\n}"
            : "=r"(done) : "r"(mbar), "r"(parity) : "memory");
    }
}

// Packed f32x2 FMA (FFMA2) — only reachable via PTX; IEEE fp32 per half.
#define FMA_F32X2(d, a, b) \
    asm("fma.rn.f32x2 %0, %1, %2, %0;" : "+l"(d) : "l"(a), "l"(b))
#define PACK_SAME(d, fbits) \
    asm("mov.b64 %0, {%1, %1};" : "=l"(d) : "r"(fbits))
#define UNPACK2(lo, hi, p) \
    asm("mov.b64 {%0, %1}, %2;" : "=f"(lo), "=f"(hi) : "l"(p))

// ---------------------------------------------------------------------------
// Kernel 1: qw = query @ W. 128 CTAs x 256 threads, 64 rows/CTA.
// Fires programmatic-launch completion at the end (PDL upstream).
// ---------------------------------------------------------------------------
__global__ __launch_bounds__(256, 2) void qw_gemm_kernel(
    const float* __restrict__ query, const float* __restrict__ W,
    const int* __restrict__ len32)
{
    extern __shared__ float smem1[];
    float* sW = smem1;                 // [128][128]
    float* sQ = smem1 + QQ * HH;       // [64][132] padded

    const int tid = threadIdx.x;
    const int b0  = blockIdx.x * 64;

    // len dtype detection: int64 values in [0,200) -> all odd dwords zero
    if (blockIdx.x == 0 && tid == 0) {
        int nz = 0;
#pragma unroll
        for (int i = 1; i < 256; i += 2) nz += (len32[i] != 0);
        g_len_is64 = (nz == 0) ? 1 : 0;
    }

    const float4* W4 = (const float4*)W;
    float4* sW4 = (float4*)sW;
#pragma unroll
    for (int i = 0; i < 16; ++i)
        sW4[tid + i * 256] = W4[tid + i * 256];

    const float4* Q4 = (const float4*)(query + (size_t)b0 * QQ);
#pragma unroll
    for (int i = 0; i < 8; ++i) {
        int idx = tid + i * 256;           // 0..2047
        int r = idx >> 5;
        int c = (idx & 31) << 2;
        float4 v = Q4[idx];
        *(float4*)&sQ[r * 132 + c] = v;
    }
    __syncthreads();

    const int j  = tid & 15;       // col octet
    const int i  = tid >> 4;       // row group (0..15)
    const int r0 = i * 4;
    const int h0 = j * 8;

    // 4 rows x 8 cols as 4x4 packed f32x2 accumulators
    uint64_t acc[4][4];
#pragma unroll
    for (int a = 0; a < 4; ++a)
#pragma unroll
        for (int c = 0; c < 4; ++c) acc[a][c] = 0ull;

#pragma unroll 4
    for (int q = 0; q < QQ; ++q) {
        const ulonglong2* wp = (const ulonglong2*)&sW[q * HH + h0];
        ulonglong2 wa = wp[0];   // {c0c1, c2c3}
        ulonglong2 wb = wp[1];   // {c4c5, c6c7}
#pragma unroll
        for (int a = 0; a < 4; ++a) {
            const uint32_t qb = __float_as_uint(sQ[(r0 + a) * 132 + q]);
            uint64_t qq; PACK_SAME(qq, qb);
            FMA_F32X2(acc[a][0], qq, wa.x);
            FMA_F32X2(acc[a][1], qq, wa.y);
            FMA_F32X2(acc[a][2], qq, wb.x);
            FMA_F32X2(acc[a][3], qq, wb.y);
        }
    }

#pragma unroll
    for (int a = 0; a < 4; ++a) {
        float o[8];
#pragma unroll
        for (int c = 0; c < 4; ++c) UNPACK2(o[2 * c], o[2 * c + 1], acc[a][c]);
        float* dst = g_qw + (size_t)(b0 + r0 + a) * HH + h0;
        float4 o0 = {o[0], o[1], o[2], o[3]};
        float4 o1 = {o[4], o[5], o[6], o[7]};
        *(float4*)dst       = o0;
        *(float4*)(dst + 4) = o1;
    }

    // PDL: all g_qw / g_len_is64 writes above are pre-trigger -> visible to
    // the dependent grid after its griddepcontrol.wait.
    asm volatile("griddepcontrol.launch_dependents;");
}

// ---------------------------------------------------------------------------
// Kernel 2: persistent, double-buffered attention pooling (PDL downstream:
// mbar init + first hist TMA issue happen BEFORE waiting on the gemm).
// grid=148 (1 CTA/SM), 640 threads (20 warps).
// ---------------------------------------------------------------------------
__global__ __launch_bounds__(NTHREADS, 1) void attn_pool_kernel(
    const float* __restrict__ hist, const void* __restrict__ hlen,
    float* __restrict__ out)
{
    extern __shared__ float smem[];
    float*  bufs[2] = { smem, smem + ROW_FLOATS };
    float*  s_logits = smem + 2 * ROW_FLOATS;          // 51200 (e_l for l>=Lb)
    float*  s_red    = s_logits + 256;                 // 51456 (20 warp sums)
    float*  s_part   = s_red + 36;                     // 51492: [20][128]
    uint64_t* mbar   = (uint64_t*)(smem + 54052);      // byte 216208, 8B aligned

    const int tid  = threadIdx.x;
    const int warp = tid >> 5;
    const int lane = tid & 31;
    const int bid  = blockIdx.x;
    const int k    = lane & 7;      // column octet (0..7)
    const int r    = lane >> 3;     // row-in-group (0..3)

    const uint32_t m0 = smem_u32(&mbar[0]);
    const uint32_t m1 = smem_u32(&mbar[1]);
    const uint32_t buf_a[2] = { smem_u32(bufs[0]), smem_u32(bufs[1]) };

    if (tid == 0) { mbar_init(m0, 1); mbar_init(m1, 1); }
    __syncthreads();

    // prologue: first row into buf0 — independent of the gemm, issue early
    if (tid == 0) {
        mbar_expect_tx(m0, ROW_BYTES);
        bulk_g2s(buf_a[0], hist + (size_t)bid * ROW_FLOATS, ROW_BYTES, m0);
    }

    // PDL: wait for gemm completion before touching g_qw / g_len_is64.
    asm volatile("griddepcontrol.wait;" ::: "memory");

    const int is64 = g_len_is64;

    uint32_t ph0 = 0, ph1 = 0;
    int it = 0;
    for (int b = bid; b < BB; b += GRID, ++it) {
        const int cur = it & 1;

        // prefetch next row into the other buffer (consumed last iteration)
        const int bn = b + GRID;
        if (bn < BB && tid == 0) {
            const uint32_t mb = cur ? m0 : m1;
            mbar_expect_tx(mb, ROW_BYTES);
            bulk_g2s(buf_a[cur ^ 1], hist + (size_t)bn * ROW_FLOATS, ROW_BYTES, mb);
        }

        // prefetch qw fragment + length while the copy runs
        const float4* qw4 = (const float4*)(g_qw + (size_t)b * HH);
        float4 qv[4];
#pragma unroll
        for (int c = 0; c < 4; ++c) qv[c] = qw4[c * 8 + k];

        int Lb;
        if (is64) Lb = (int)((const long long*)hlen)[b];
        else      Lb = ((const int*)hlen)[b];
        const int g0 = Lb >> 2;      // first group with any unmasked row

        // wait current buffer
        if (cur == 0) { mbar_wait(m0, ph0); ph0 ^= 1; }
        else          { mbar_wait(m1, ph1); ph1 ^= 1; }

        const float4* s4 = (const float4*)bufs[cur];

        // ---- pass 1: e_l = exp(logit_l) for l >= Lb only; masked groups
        // skipped entirely, active groups rebalanced across warps.
        float wsum = 0.f;
        for (int g = g0 + warp; g < 50; g += NWARPS) {
            const int l = g * 4 + r;
            const float4* row4 = s4 + l * 32;
            float p = 0.f;
#pragma unroll
            for (int c = 0; c < 4; ++c) {
                float4 v = row4[c * 8 + k];
                p += v.x * qv[c].x + v.y * qv[c].y + v.z * qv[c].z + v.w * qv[c].w;
            }
            p += __shfl_xor_sync(0xffffffffu, p, 4);
            p += __shfl_xor_sync(0xffffffffu, p, 2);
            p += __shfl_xor_sync(0xffffffffu, p, 1);
            float e = 0.f;
            if (l >= Lb) e = __expf(p);        // boundary-group masked lanes: 0
            if (k == 0) { s_logits[l] = e; wsum += e; }
        }
        // combine k==0 lanes (0,8,16,24)
        wsum += __shfl_xor_sync(0xffffffffu, wsum, 16);
        wsum += __shfl_xor_sync(0xffffffffu, wsum, 8);
        if (lane == 0) s_red[warp] = wsum;
        __syncthreads();

        // private 1/tot: masked rows contribute exactly 1.0 each (exp(1e-9))
        float t0 = 0.f, t1 = 0.f, t2 = 0.f, t3 = 0.f;
#pragma unroll
        for (int w = 0; w < NWARPS; w += 4) {
            t0 += s_red[w]; t1 += s_red[w + 1]; t2 += s_red[w + 2]; t3 += s_red[w + 3];
        }
        const float inv = __frcp_rn((float)Lb + ((t0 + t1) + (t2 + t3)));

        // ---- pass 2: fully unrolled 10 iterations (200/20) -> all LDS.128
        // batched up-front (MLP ~10 instead of ~2).
        float4 a4 = {0.f, 0.f, 0.f, 0.f};
#pragma unroll
        for (int i = 0; i < 10; ++i) {
            const int l = warp + i * NWARPS;
            const float sc = (l < Lb) ? 1.0f : s_logits[l];
            float4 v = s4[l * 32 + lane];
            a4.x = fmaf(sc, v.x, a4.x);
            a4.y = fmaf(sc, v.y, a4.y);
            a4.z = fmaf(sc, v.z, a4.z);
            a4.w = fmaf(sc, v.w, a4.w);
        }
        a4.x *= inv; a4.y *= inv; a4.z *= inv; a4.w *= inv;
        ((float4*)s_part)[warp * 32 + lane] = a4;
        __syncthreads();   // all buf[cur] reads done after this

        // ---- final reduce: 128 threads, conflict-free scalar columns ----
        if (tid < HH) {
            float vsum = 0.f;
#pragma unroll
            for (int g = 0; g < NWARPS; ++g) vsum += s_part[g * HH + tid];
            out[(size_t)b * HH + tid] = vsum;
        }
    }
}

// ---------------------------------------------------------------------------
extern "C" void kernel_launch(void* const* d_in, const int* in_sizes, int n_in,
                              void* d_out, int out_size) {
    // Bind inputs BY ELEMENT COUNT (all distinct) — immune to ordering.
    const float* query = nullptr;   // 1048576
    const float* hist  = nullptr;   // 209715200
    const void*  hlen  = nullptr;   // 8192
    const float* W     = nullptr;   // 16384
    for (int i = 0; i < n_in; ++i) {
        switch (in_sizes[i]) {
            case BB * QQ:      query = (const float*)d_in[i]; break;
            case BB * LL * HH: hist  = (const float*)d_in[i]; break;
            case BB:           hlen  = d_in[i];               break;
            case QQ * HH:      W     = (const float*)d_in[i]; break;
            default: break;
        }
    }
    float* out = (float*)d_out;

    const int smem1 = (QQ * HH + 64 * 132) * (int)sizeof(float);   // 99328
    const int smem2 = 54052 * 4 + 64;                               // 216272

    cudaFuncSetAttribute(qw_gemm_kernel,
                         cudaFuncAttributeMaxDynamicSharedMemorySize, smem1);
    cudaFuncSetAttribute(attn_pool_kernel,
                         cudaFuncAttributeMaxDynamicSharedMemorySize, smem2);

    qw_gemm_kernel<<<BB / 64, 256, smem1>>>(query, W, (const int*)hlen);

    // PDL launch: attn may start while gemm drains; it waits via
    // griddepcontrol.wait before touching gemm outputs.
    cudaLaunchConfig_t cfg = {};
    cfg.gridDim  = dim3(GRID, 1, 1);
    cfg.blockDim = dim3(NTHREADS, 1, 1);
    cfg.dynamicSmemBytes = smem2;
    cfg.stream = 0;
    cudaLaunchAttribute attr[1];
    attr[0].id = cudaLaunchAttributeProgrammaticStreamSerialization;
    attr[0].val.programmaticStreamSerializationAllowed = 1;
    cfg.attrs = attr;
    cfg.numAttrs = 1;
    cudaLaunchKernelEx(&cfg, attn_pool_kernel, hist, (const void*)hlen, out);
}